// round 6
// baseline (speedup 1.0000x reference)
#include <cuda_runtime.h>
#include <cuda_bf16.h>
#include <cstdint>
#include <math.h>

#define L_LAYERS 16
#define QD 2048
#define BATCH 4096
#define NMAT 17  // 16 layers + measurement basis

#if defined(__CUDA_ARCH_FEAT_SM103_ALL) || defined(__CUDA_ARCH_FEAT_SM100_ALL) || \
    (defined(__CUDA_ARCH_SPECIFIC__) && (__CUDA_ARCH_SPECIFIC__ >= 1000))
#define HAS_TCGEN05 1
#else
#define HAS_TCGEN05 0
#endif

// ---------------------------------------------------------------------------
// Device scratch. Operands in K-staged, SW64-pre-swizzled layout:
//   [K/32 stages][rows][32 bf16]  -> per-stage CTA tile is contiguous, fetched
// with one cp.async.bulk, landing exactly in SW64 layout for the MMA.
// ---------------------------------------------------------------------------
#define KSTAGES (QD / 32)  // 64
__device__ __nv_bfloat16 g_Wst_hi[(size_t)NMAT * KSTAGES * QD * 32];
__device__ __nv_bfloat16 g_Wst_lo[(size_t)NMAT * KSTAGES * QD * 32];
__device__ __nv_bfloat16 g_Ast_hi[2][(size_t)KSTAGES * BATCH * 32];
__device__ __nv_bfloat16 g_Ast_lo[2][(size_t)KSTAGES * BATCH * 32];
__device__ float g_scales[L_LAYERS][QD];
// per (layer, M-group, N-cta, chunk) arrival counters (8 epilogue warps each)
__device__ int g_flags[NMAT][16][8][8];

// ---------------------------------------------------------------------------
// PTX helpers
// ---------------------------------------------------------------------------
__device__ __forceinline__ uint32_t smem_u32(const void* p) {
    uint32_t a;
    asm("{ .reg .u64 t; cvta.to.shared.u64 t, %1; cvt.u32.u64 %0, t; }"
        : "=r"(a) : "l"(p));
    return a;
}

__device__ __forceinline__ uint32_t elect_one_pred() {
    uint32_t pred;
    asm volatile(
        "{\n\t.reg .pred p;\n\telect.sync _|p, 0xFFFFFFFF;\n\t"
        "selp.b32 %0, 1, 0, p;\n\t}"
        : "=r"(pred));
    return pred;
}

#define MBARRIER_INIT(addr, count) \
    asm volatile("mbarrier.init.shared.b64 [%0], %1;" \
                 :: "r"((uint32_t)(addr)), "r"((uint32_t)(count)) : "memory")

#define MBARRIER_EXPECT_TX(addr, tx) \
    asm volatile("mbarrier.arrive.expect_tx.shared.b64 _, [%0], %1;" \
                 :: "r"((uint32_t)(addr)), "r"((uint32_t)(tx)) : "memory")

#define MBARRIER_WAIT_PARITY(mbar_smem_addr, phase_parity) do { \
    uint32_t _mbar = (uint32_t)(mbar_smem_addr); \
    uint32_t _parity = (uint32_t)(phase_parity); \
    uint32_t _done; \
    asm volatile( \
        "{\n\t.reg .pred p;\n\t" \
        "mbarrier.try_wait.parity.acquire.cta.shared::cta.b64 p, [%1], %2;\n\t" \
        "selp.b32 %0, 1, 0, p;\n\t}" \
        : "=r"(_done) : "r"(_mbar), "r"(_parity) : "memory"); \
    if (!_done) { \
        asm volatile( \
            "{\n\t.reg .pred P1;\n\t" \
            "WAIT_LOOP_%=:\n\t" \
            "mbarrier.try_wait.parity.acquire.cta.shared::cta.b64 P1, [%0], %1, 0x989680;\n\t" \
            "@P1 bra.uni WAIT_DONE_%=;\n\t" \
            "bra.uni WAIT_LOOP_%=;\n\t" \
            "WAIT_DONE_%=:\n\t}" \
            :: "r"(_mbar), "r"(_parity) : "memory"); \
    } \
} while (0)

__device__ __forceinline__ void bulk_cp(uint32_t dst, const void* src,
                                        uint32_t bytes, uint32_t mbar) {
    asm volatile(
        "cp.async.bulk.shared::cta.global.mbarrier::complete_tx::bytes "
        "[%0], [%1], %2, [%3];"
        :: "r"(dst), "l"(src), "r"(bytes), "r"(mbar) : "memory");
}

#if HAS_TCGEN05
#define TCGEN05_ALLOC(smem_result_addr, nCols) \
    asm volatile("tcgen05.alloc.cta_group::1.sync.aligned.shared::cta.b32 [%0], %1;" \
                 :: "r"((uint32_t)(smem_result_addr)), "r"((uint32_t)(nCols)) : "memory")
#define TCGEN05_DEALLOC(tmem_addr, nCols) \
    asm volatile("tcgen05.dealloc.cta_group::1.sync.aligned.b32 %0, %1;" \
                 :: "r"(tmem_addr), "r"((uint32_t)(nCols)))
#define TCGEN05_RELINQUISH() \
    asm volatile("tcgen05.relinquish_alloc_permit.cta_group::1.sync.aligned;")
#define TCGEN05_COMMIT(mbar) \
    asm volatile("tcgen05.commit.cta_group::1.mbarrier::arrive::one.shared::cluster.b64 [%0];" \
                 :: "r"((uint32_t)(mbar)) : "memory")
#define TCGEN05_FENCE_AFTER() \
    asm volatile("tcgen05.fence::after_thread_sync;" ::: "memory")
#define TCGEN05_FENCE_BEFORE() \
    asm volatile("tcgen05.fence::before_thread_sync;" ::: "memory")
#define TCGEN05_WAIT_LD() \
    asm volatile("tcgen05.wait::ld.sync.aligned;" ::: "memory")

#define TCGEN05_LD_32X32B_X32(r, tmem_addr) \
    asm volatile( \
        "tcgen05.ld.sync.aligned.32x32b.x32.b32 " \
        "{%0, %1, %2, %3, %4, %5, %6, %7, " \
        " %8, %9, %10, %11, %12, %13, %14, %15, " \
        " %16, %17, %18, %19, %20, %21, %22, %23, " \
        " %24, %25, %26, %27, %28, %29, %30, %31}, [%32];" \
        : "=r"((r)[0]),  "=r"((r)[1]),  "=r"((r)[2]),  "=r"((r)[3]), \
          "=r"((r)[4]),  "=r"((r)[5]),  "=r"((r)[6]),  "=r"((r)[7]), \
          "=r"((r)[8]),  "=r"((r)[9]),  "=r"((r)[10]), "=r"((r)[11]), \
          "=r"((r)[12]), "=r"((r)[13]), "=r"((r)[14]), "=r"((r)[15]), \
          "=r"((r)[16]), "=r"((r)[17]), "=r"((r)[18]), "=r"((r)[19]), \
          "=r"((r)[20]), "=r"((r)[21]), "=r"((r)[22]), "=r"((r)[23]), \
          "=r"((r)[24]), "=r"((r)[25]), "=r"((r)[26]), "=r"((r)[27]), \
          "=r"((r)[28]), "=r"((r)[29]), "=r"((r)[30]), "=r"((r)[31]) \
        : "r"(tmem_addr))

__device__ __forceinline__ void mma_f16_ss(uint32_t d, uint64_t da, uint64_t db,
                                           uint32_t idesc, uint32_t en) {
    asm volatile(
        "{\n\t.reg .pred p;\n\tsetp.ne.u32 p, %4, 0;\n\t"
        "tcgen05.mma.cta_group::1.kind::f16 [%0], %1, %2, %3, {%5,%5,%5,%5}, p;\n\t}"
        :: "r"(d), "l"(da), "l"(db), "r"(idesc), "r"(en), "r"(0u) : "memory");
}
#endif  // HAS_TCGEN05

// SW64 smem matrix descriptor: layout=4 (SW64), version=1, SBO=32, LBO=1.
static constexpr uint64_t DESC_SW64_BASE =
    (uint64_t(4) << 61) | (uint64_t(1) << 46) | (uint64_t(32) << 32) | (uint64_t(1) << 16);
#define MAKE_DESC64(a) (DESC_SW64_BASE | ((uint64_t)((a) >> 4) & 0x3FFF))

// ---------------------------------------------------------------------------
// Prep kernels (staged layout, SW64 swizzle pre-applied: unit u ^= (row>>1)&3)
// ---------------------------------------------------------------------------
__global__ void prep_small_kernel(const float* __restrict__ angles) {
    int idx = blockIdx.x * blockDim.x + threadIdx.x;
    if (idx < NMAT * 16 * 8 * 8) ((int*)g_flags)[idx] = 0;
    if (idx < L_LAYERS * QD) {
        const float* a = angles + idx * 3;
        (&g_scales[0][0])[idx] = cosf(0.5f * a[0]) * cosf(0.5f * a[1]) * cosf(0.5f * a[2]);
    }
}

__global__ void convert_weights_staged(const float* __restrict__ weights,
                                       const float* __restrict__ meas) {
    __shared__ __nv_bfloat16 sh[8][1024];
    __shared__ __nv_bfloat16 sl[8][1024];
    const int m = blockIdx.z;
    const float* src = (m < L_LAYERS) ? (weights + (size_t)m * QD * QD) : meas;
    const int sK = blockIdx.x;
    const int w = threadIdx.x >> 5, ln = threadIdx.x & 31;
    const int n0 = (blockIdx.y * 8 + w) * 32;
    const int uperm = (ln >> 1) & 3;
#pragma unroll 4
    for (int j = 0; j < 32; ++j) {
        float x = src[(size_t)(sK * 32 + j) * QD + n0 + ln];
        __nv_bfloat16 h = __float2bfloat16(x);
        __nv_bfloat16 l = __float2bfloat16(x - __bfloat162float(h));
        int u = j >> 3, e = j & 7;
        int pos = ln * 32 + ((u ^ uperm) << 3) + e;
        sh[w][pos] = h;
        sl[w][pos] = l;
    }
    __syncwarp();
    size_t rowbase = ((size_t)m * KSTAGES + sK) * QD + n0;
    uint4* dh = (uint4*)(g_Wst_hi + rowbase * 32);
    uint4* dl = (uint4*)(g_Wst_lo + rowbase * 32);
    const uint4* s4h = (const uint4*)sh[w];
    const uint4* s4l = (const uint4*)sl[w];
#pragma unroll
    for (int p = 0; p < 4; ++p) {
        dh[ln + 32 * p] = s4h[ln + 32 * p];
        dl[ln + 32 * p] = s4l[ln + 32 * p];
    }
}

__global__ void convert_input_staged(const float* __restrict__ in) {
    __shared__ __nv_bfloat16 sh[8][1024];
    __shared__ __nv_bfloat16 sl[8][1024];
    const int sK = blockIdx.x;
    const int w = threadIdx.x >> 5, ln = threadIdx.x & 31;
    const int r0 = (blockIdx.y * 8 + w) * 32;
    const float sc = g_scales[0][sK * 32 + ln];
    const int u = ln >> 3, e = ln & 7;
#pragma unroll 4
    for (int j = 0; j < 32; ++j) {
        float x = in[(size_t)(r0 + j) * QD + sK * 32 + ln] * sc;
        __nv_bfloat16 h = __float2bfloat16(x);
        __nv_bfloat16 l = __float2bfloat16(x - __bfloat162float(h));
        int pos = j * 32 + ((u ^ ((j >> 1) & 3)) << 3) + e;
        sh[w][pos] = h;
        sl[w][pos] = l;
    }
    __syncwarp();
    size_t rowbase = (size_t)sK * BATCH + r0;
    uint4* dh = (uint4*)(g_Ast_hi[0] + rowbase * 32);
    uint4* dl = (uint4*)(g_Ast_lo[0] + rowbase * 32);
    const uint4* s4h = (const uint4*)sh[w];
    const uint4* s4l = (const uint4*)sl[w];
#pragma unroll
    for (int p = 0; p < 4; ++p) {
        dh[ln + 32 * p] = s4h[ln + 32 * p];
        dl[ln + 32 * p] = s4l[ln + 32 * p];
    }
}

// ---------------------------------------------------------------------------
// Persistent 17-layer chained GEMM. Grid (8,16) = 128 CTAs = one wave.
// CTA tile 256x256 for all layers. Per-chunk gmem flags pipeline the layer
// transition: stage k of layer l+1 only needs CTA (mi, k/8)'s chunk (k%8).
// Warps 0-7: epilogue. Warp 8: bulk producer. Warp 9: MMA.
// ---------------------------------------------------------------------------
#define BM 256
#define BN 256
#define NSTAGE 3
#define TILE_B 16384
#define STAGE_B (4 * TILE_B)  // 64KB
#define K_ITERS KSTAGES       // 64
#define MMA_IDESC 0x8400490u  // F32 acc, BF16 a/b, M=128, N=256

__global__ __launch_bounds__(320, 1)
void qgemm_persistent(float* __restrict__ outF) {
#if HAS_TCGEN05
    extern __shared__ __align__(1024) char smem_dyn[];
    __shared__ __align__(8) unsigned long long s_bars[7];
    __shared__ uint32_t s_tmem;

    const int tid = threadIdx.x;
    const int wid = tid >> 5;
    const int lid = tid & 31;

    const uint32_t raw = smem_u32(smem_dyn);
    const uint32_t smem_base = (raw + 1023u) & ~1023u;

    uint32_t bar_full[3], bar_empty[3], bar_done;
#pragma unroll
    for (int i = 0; i < 3; ++i) {
        bar_full[i]  = smem_u32(&s_bars[i]);
        bar_empty[i] = smem_u32(&s_bars[3 + i]);
    }
    bar_done = smem_u32(&s_bars[6]);

    if (tid == 0) {
#pragma unroll
        for (int i = 0; i < 3; ++i) {
            MBARRIER_INIT(bar_full[i], 1);
            MBARRIER_INIT(bar_empty[i], 1);
        }
        MBARRIER_INIT(bar_done, 1);
    }
    if (wid == 8) TCGEN05_ALLOC(smem_u32(&s_tmem), 512);
    __syncthreads();
    const uint32_t tmem_d = s_tmem;

    const int mi = blockIdx.y;
    const int ni = blockIdx.x;
    const int blockN = ni * BN;
    const int blockM = mi * BM;
    const size_t MATB = (size_t)KSTAGES * QD * 64;

    if (wid == 8) {
        // ---- producer -------------------------------------------------
        if (elect_one_pred()) {
            int s = 0, w = 0;
            for (int it = 0; it < NMAT * K_ITERS; ++it) {
                const int l = it >> 6, k = it & 63;
                if (it >= NSTAGE) MBARRIER_WAIT_PARITY(bar_empty[s], (w + 1) & 1);
                const uint32_t stage = smem_base + s * STAGE_B;
                MBARRIER_EXPECT_TX(bar_full[s], STAGE_B);
                // B (weights): no dependency, issue first
                const size_t boff = (size_t)l * MATB + ((size_t)k * QD + blockN) * 64;
                bulk_cp(stage + 2 * TILE_B, (const char*)g_Wst_hi + boff, TILE_B, bar_full[s]);
                bulk_cp(stage + 3 * TILE_B, (const char*)g_Wst_lo + boff, TILE_B, bar_full[s]);
                // A (state): wait for producing CTA's chunk of prev layer
                if (l > 0) {
                    const int* cnt = &g_flags[l - 1][mi][k >> 3][k & 7];
                    int v;
                    do {
                        asm volatile("ld.acquire.gpu.global.b32 %0, [%1];"
                                     : "=r"(v) : "l"(cnt) : "memory");
                    } while (v < 8);
                    asm volatile("fence.proxy.async;" ::: "memory");
                }
                const int pb = l & 1;
                const size_t aoff = ((size_t)k * BATCH + blockM) * 64;
                bulk_cp(stage,          (const char*)g_Ast_hi[pb] + aoff, TILE_B, bar_full[s]);
                bulk_cp(stage + TILE_B, (const char*)g_Ast_lo[pb] + aoff, TILE_B, bar_full[s]);
                if (++s == NSTAGE) { s = 0; ++w; }
            }
        }
    } else if (wid == 9) {
        // ---- MMA warp ---------------------------------------------------
        int s = 0, w = 0;
        for (int l = 0; l < NMAT; ++l) {
            asm volatile("bar.sync 1, 288;" ::: "memory");  // TMEM free handoff
            TCGEN05_FENCE_AFTER();
            for (int k = 0; k < K_ITERS; ++k) {
                MBARRIER_WAIT_PARITY(bar_full[s], w & 1);
                const uint32_t stage = smem_base + s * STAGE_B;
                if (elect_one_pred()) {
                    const uint64_t dBh = MAKE_DESC64(stage + 2 * TILE_B);
                    const uint64_t dBl = MAKE_DESC64(stage + 3 * TILE_B);
#pragma unroll
                    for (int h = 0; h < 2; ++h) {
                        const uint64_t dAh = MAKE_DESC64(stage + h * 8192);
                        const uint64_t dAl = MAKE_DESC64(stage + TILE_B + h * 8192);
                        const uint32_t d = tmem_d + h * 256;
#pragma unroll
                        for (int c = 0; c < 2; ++c) {
                            uint32_t en0 = (k == 0 && c == 0) ? 0u : 1u;
                            mma_f16_ss(d, dAh + 2 * c, dBh + 2 * c, MMA_IDESC, en0);
                            mma_f16_ss(d, dAh + 2 * c, dBl + 2 * c, MMA_IDESC, 1);
                            mma_f16_ss(d, dAl + 2 * c, dBh + 2 * c, MMA_IDESC, 1);
                        }
                    }
                    TCGEN05_COMMIT(bar_empty[s]);
                }
                if (++s == NSTAGE) { s = 0; ++w; }
            }
            if (elect_one_pred()) TCGEN05_COMMIT(bar_done);
        }
    } else {
        // ---- epilogue warps 0-7 ----------------------------------------
        const int half = wid >> 2;
        const int rbase = blockM + half * 128 + (wid & 3) * 32;
        const int row = rbase + lid;
        const int uperm = (lid >> 1) & 3;
        for (int l = 0; l < NMAT; ++l) {
            asm volatile("bar.sync 1, 288;" ::: "memory");
            MBARRIER_WAIT_PARITY(bar_done, l & 1);
            TCGEN05_FENCE_AFTER();
            const float* scaleNext = (l < L_LAYERS - 1) ? g_scales[l + 1] : nullptr;
            const int fpout = (l == NMAT - 1);
            const int wb = (l + 1) & 1;
            __nv_bfloat16* outHi = g_Ast_hi[wb];
            __nv_bfloat16* outLo = g_Ast_lo[wb];
#pragma unroll 1
            for (int ch = 0; ch < 8; ++ch) {
                uint32_t regs[32];
                TCGEN05_LD_32X32B_X32(regs, tmem_d + half * 256 + ch * 32);
                TCGEN05_WAIT_LD();
                const int c0 = blockN + ch * 32;
                if (fpout) {
                    float* dst = outF + (size_t)row * QD + c0;
#pragma unroll
                    for (int g = 0; g < 8; ++g)
                        *(float4*)(dst + g * 4) = make_float4(
                            __uint_as_float(regs[g * 4 + 0]), __uint_as_float(regs[g * 4 + 1]),
                            __uint_as_float(regs[g * 4 + 2]), __uint_as_float(regs[g * 4 + 3]));
                } else {
                    uint32_t hp[16], lp[16];
#pragma unroll
                    for (int q = 0; q < 16; ++q) {
                        float v0 = __uint_as_float(regs[2 * q]);
                        float v1 = __uint_as_float(regs[2 * q + 1]);
                        if (scaleNext) {
                            const float2 s2 = *(const float2*)(scaleNext + c0 + 2 * q);
                            v0 *= s2.x;
                            v1 *= s2.y;
                        }
                        // truncation split: hi = top 16 bits, lo = v - hi
                        uint32_t b0 = __float_as_uint(v0), b1 = __float_as_uint(v1);
                        float lo0 = v0 - __uint_as_float(b0 & 0xFFFF0000u);
                        float lo1 = v1 - __uint_as_float(b1 & 0xFFFF0000u);
                        uint32_t h;
                        asm("prmt.b32 %0, %1, %2, 0x7632;" : "=r"(h) : "r"(b0), "r"(b1));
                        hp[q] = h;
                        uint32_t lpk;
                        asm("cvt.rn.bf16x2.f32 %0, %1, %2;" : "=r"(lpk) : "f"(lo1), "f"(lo0));
                        lp[q] = lpk;
                    }
                    // direct swizzled stores: row is 64B in staged layout
                    const int sK = c0 >> 5;
                    char* baseh = (char*)outHi + ((size_t)sK * BATCH + row) * 64;
                    char* basel = (char*)outLo + ((size_t)sK * BATCH + row) * 64;
#pragma unroll
                    for (int u = 0; u < 4; ++u) {
                        int up = (u ^ uperm) << 4;
                        *(uint4*)(baseh + up) =
                            make_uint4(hp[4 * u], hp[4 * u + 1], hp[4 * u + 2], hp[4 * u + 3]);
                        *(uint4*)(basel + up) =
                            make_uint4(lp[4 * u], lp[4 * u + 1], lp[4 * u + 2], lp[4 * u + 3]);
                    }
                    __syncwarp();
                    if (lid == 0) {
                        asm volatile("red.release.gpu.global.add.s32 [%0], 1;"
                                     :: "l"(&g_flags[l][mi][ni][ch]) : "memory");
                    }
                }
            }
            TCGEN05_FENCE_BEFORE();
        }
    }

    __syncthreads();
    if (wid == 8) {
        TCGEN05_RELINQUISH();
        TCGEN05_DEALLOC(tmem_d, 512);
    }
#endif  // HAS_TCGEN05
}

// ---------------------------------------------------------------------------
// Launch
// ---------------------------------------------------------------------------
extern "C" void kernel_launch(void* const* d_in, const int* in_sizes, int n_in,
                              void* d_out, int out_size) {
    const float* input_state = (const float*)d_in[0];
    const float* angles      = (const float*)d_in[1];
    const float* weights     = (const float*)d_in[2];
    const float* meas_basis  = (const float*)d_in[3];
    float* out = (float*)d_out;
    (void)in_sizes; (void)n_in; (void)out_size;

    const size_t dyn = NSTAGE * STAGE_B + 1024;  // 193 KB
    cudaFuncSetAttribute(qgemm_persistent, cudaFuncAttributeMaxDynamicSharedMemorySize, dyn);

    prep_small_kernel<<<128, 256>>>(angles);
    convert_weights_staged<<<dim3(KSTAGES, QD / 256, NMAT), 256>>>(weights, meas_basis);
    convert_input_staged<<<dim3(KSTAGES, BATCH / 256), 256>>>(input_state);

    dim3 grid(QD / BN, BATCH / BM);  // (8, 16) = 128 CTAs, one wave
    qgemm_persistent<<<grid, 320, dyn>>>(out);
}

// round 7
// speedup vs baseline: 1.0810x; 1.0810x over previous
#include <cuda_runtime.h>
#include <cuda_bf16.h>
#include <cstdint>
#include <math.h>

#define L_LAYERS 16
#define QD 2048
#define BATCH 4096
#define NMAT 17  // 16 layers + measurement basis

#if defined(__CUDA_ARCH_FEAT_SM103_ALL) || defined(__CUDA_ARCH_FEAT_SM100_ALL) || \
    (defined(__CUDA_ARCH_SPECIFIC__) && (__CUDA_ARCH_SPECIFIC__ >= 1000))
#define HAS_TCGEN05 1
#else
#define HAS_TCGEN05 0
#endif

// ---------------------------------------------------------------------------
// Device scratch. Operands in K-staged, SW64-pre-swizzled layout:
//   [K/32 stages][rows][32 bf16]  -> per-stage CTA tile is contiguous, fetched
// with one cp.async.bulk, landing exactly in SW64 layout for the MMA.
// ---------------------------------------------------------------------------
#define KSTAGES (QD / 32)  // 64
__device__ __nv_bfloat16 g_Wst_hi[(size_t)NMAT * KSTAGES * QD * 32];
__device__ __nv_bfloat16 g_Wst_lo[(size_t)NMAT * KSTAGES * QD * 32];
__device__ __nv_bfloat16 g_Ast_hi[2][(size_t)KSTAGES * BATCH * 32];
__device__ __nv_bfloat16 g_Ast_lo[2][(size_t)KSTAGES * BATCH * 32];
__device__ float g_scales[L_LAYERS][QD];
// per (layer, M-group, N-cta, chunk) arrival counters (8 epilogue warps each)
__device__ int g_flags[NMAT][16][8][8];

// ---------------------------------------------------------------------------
// PTX helpers
// ---------------------------------------------------------------------------
__device__ __forceinline__ uint32_t smem_u32(const void* p) {
    uint32_t a;
    asm("{ .reg .u64 t; cvta.to.shared.u64 t, %1; cvt.u32.u64 %0, t; }"
        : "=r"(a) : "l"(p));
    return a;
}

__device__ __forceinline__ uint32_t elect_one_pred() {
    uint32_t pred;
    asm volatile(
        "{\n\t.reg .pred p;\n\telect.sync _|p, 0xFFFFFFFF;\n\t"
        "selp.b32 %0, 1, 0, p;\n\t}"
        : "=r"(pred));
    return pred;
}

#define MBARRIER_INIT(addr, count) \
    asm volatile("mbarrier.init.shared.b64 [%0], %1;" \
                 :: "r"((uint32_t)(addr)), "r"((uint32_t)(count)) : "memory")

#define MBARRIER_EXPECT_TX(addr, tx) \
    asm volatile("mbarrier.arrive.expect_tx.shared.b64 _, [%0], %1;" \
                 :: "r"((uint32_t)(addr)), "r"((uint32_t)(tx)) : "memory")

#define MBARRIER_WAIT_PARITY(mbar_smem_addr, phase_parity) do { \
    uint32_t _mbar = (uint32_t)(mbar_smem_addr); \
    uint32_t _parity = (uint32_t)(phase_parity); \
    uint32_t _done; \
    asm volatile( \
        "{\n\t.reg .pred p;\n\t" \
        "mbarrier.try_wait.parity.acquire.cta.shared::cta.b64 p, [%1], %2;\n\t" \
        "selp.b32 %0, 1, 0, p;\n\t}" \
        : "=r"(_done) : "r"(_mbar), "r"(_parity) : "memory"); \
    if (!_done) { \
        asm volatile( \
            "{\n\t.reg .pred P1;\n\t" \
            "WAIT_LOOP_%=:\n\t" \
            "mbarrier.try_wait.parity.acquire.cta.shared::cta.b64 P1, [%0], %1, 0x989680;\n\t" \
            "@P1 bra.uni WAIT_DONE_%=;\n\t" \
            "bra.uni WAIT_LOOP_%=;\n\t" \
            "WAIT_DONE_%=:\n\t}" \
            :: "r"(_mbar), "r"(_parity) : "memory"); \
    } \
} while (0)

__device__ __forceinline__ void bulk_cp(uint32_t dst, const void* src,
                                        uint32_t bytes, uint32_t mbar) {
    asm volatile(
        "cp.async.bulk.shared::cta.global.mbarrier::complete_tx::bytes "
        "[%0], [%1], %2, [%3];"
        :: "r"(dst), "l"(src), "r"(bytes), "r"(mbar) : "memory");
}

#if HAS_TCGEN05
#define TCGEN05_ALLOC(smem_result_addr, nCols) \
    asm volatile("tcgen05.alloc.cta_group::1.sync.aligned.shared::cta.b32 [%0], %1;" \
                 :: "r"((uint32_t)(smem_result_addr)), "r"((uint32_t)(nCols)) : "memory")
#define TCGEN05_DEALLOC(tmem_addr, nCols) \
    asm volatile("tcgen05.dealloc.cta_group::1.sync.aligned.b32 %0, %1;" \
                 :: "r"(tmem_addr), "r"((uint32_t)(nCols)))
#define TCGEN05_RELINQUISH() \
    asm volatile("tcgen05.relinquish_alloc_permit.cta_group::1.sync.aligned;")
#define TCGEN05_COMMIT(mbar) \
    asm volatile("tcgen05.commit.cta_group::1.mbarrier::arrive::one.shared::cluster.b64 [%0];" \
                 :: "r"((uint32_t)(mbar)) : "memory")
#define TCGEN05_FENCE_AFTER() \
    asm volatile("tcgen05.fence::after_thread_sync;" ::: "memory")
#define TCGEN05_FENCE_BEFORE() \
    asm volatile("tcgen05.fence::before_thread_sync;" ::: "memory")
#define TCGEN05_WAIT_LD() \
    asm volatile("tcgen05.wait::ld.sync.aligned;" ::: "memory")

#define TCGEN05_LD_32X32B_X32(r, tmem_addr) \
    asm volatile( \
        "tcgen05.ld.sync.aligned.32x32b.x32.b32 " \
        "{%0, %1, %2, %3, %4, %5, %6, %7, " \
        " %8, %9, %10, %11, %12, %13, %14, %15, " \
        " %16, %17, %18, %19, %20, %21, %22, %23, " \
        " %24, %25, %26, %27, %28, %29, %30, %31}, [%32];" \
        : "=r"((r)[0]),  "=r"((r)[1]),  "=r"((r)[2]),  "=r"((r)[3]), \
          "=r"((r)[4]),  "=r"((r)[5]),  "=r"((r)[6]),  "=r"((r)[7]), \
          "=r"((r)[8]),  "=r"((r)[9]),  "=r"((r)[10]), "=r"((r)[11]), \
          "=r"((r)[12]), "=r"((r)[13]), "=r"((r)[14]), "=r"((r)[15]), \
          "=r"((r)[16]), "=r"((r)[17]), "=r"((r)[18]), "=r"((r)[19]), \
          "=r"((r)[20]), "=r"((r)[21]), "=r"((r)[22]), "=r"((r)[23]), \
          "=r"((r)[24]), "=r"((r)[25]), "=r"((r)[26]), "=r"((r)[27]), \
          "=r"((r)[28]), "=r"((r)[29]), "=r"((r)[30]), "=r"((r)[31]) \
        : "r"(tmem_addr))

__device__ __forceinline__ void mma_f16_ss(uint32_t d, uint64_t da, uint64_t db,
                                           uint32_t idesc, uint32_t en) {
    asm volatile(
        "{\n\t.reg .pred p;\n\tsetp.ne.u32 p, %4, 0;\n\t"
        "tcgen05.mma.cta_group::1.kind::f16 [%0], %1, %2, %3, {%5,%5,%5,%5}, p;\n\t}"
        :: "r"(d), "l"(da), "l"(db), "r"(idesc), "r"(en), "r"(0u) : "memory");
}
#endif  // HAS_TCGEN05

// SW64 smem matrix descriptor: layout=4 (SW64), version=1, SBO=32, LBO=1.
static constexpr uint64_t DESC_SW64_BASE =
    (uint64_t(4) << 61) | (uint64_t(1) << 46) | (uint64_t(32) << 32) | (uint64_t(1) << 16);
#define MAKE_DESC64(a) (DESC_SW64_BASE | ((uint64_t)((a) >> 4) & 0x3FFF))

// ---------------------------------------------------------------------------
// Prep kernels (staged layout, SW64 swizzle pre-applied: unit u ^= (row>>1)&3)
// ---------------------------------------------------------------------------
__global__ void prep_small_kernel(const float* __restrict__ angles) {
    int idx = blockIdx.x * blockDim.x + threadIdx.x;
    if (idx < NMAT * 16 * 8 * 8) ((int*)g_flags)[idx] = 0;
    if (idx < L_LAYERS * QD) {
        const float* a = angles + idx * 3;
        (&g_scales[0][0])[idx] = cosf(0.5f * a[0]) * cosf(0.5f * a[1]) * cosf(0.5f * a[2]);
    }
}

__global__ void convert_weights_staged(const float* __restrict__ weights,
                                       const float* __restrict__ meas) {
    __shared__ __nv_bfloat16 sh[8][1024];
    __shared__ __nv_bfloat16 sl[8][1024];
    const int m = blockIdx.z;
    const float* src = (m < L_LAYERS) ? (weights + (size_t)m * QD * QD) : meas;
    const int sK = blockIdx.x;
    const int w = threadIdx.x >> 5, ln = threadIdx.x & 31;
    const int n0 = (blockIdx.y * 8 + w) * 32;
    const int uperm = (ln >> 1) & 3;
#pragma unroll 4
    for (int j = 0; j < 32; ++j) {
        float x = src[(size_t)(sK * 32 + j) * QD + n0 + ln];
        __nv_bfloat16 h = __float2bfloat16(x);
        __nv_bfloat16 l = __float2bfloat16(x - __bfloat162float(h));
        int u = j >> 3, e = j & 7;
        int pos = ln * 32 + ((u ^ uperm) << 3) + e;
        sh[w][pos] = h;
        sl[w][pos] = l;
    }
    __syncwarp();
    size_t rowbase = ((size_t)m * KSTAGES + sK) * QD + n0;
    uint4* dh = (uint4*)(g_Wst_hi + rowbase * 32);
    uint4* dl = (uint4*)(g_Wst_lo + rowbase * 32);
    const uint4* s4h = (const uint4*)sh[w];
    const uint4* s4l = (const uint4*)sl[w];
#pragma unroll
    for (int p = 0; p < 4; ++p) {
        dh[ln + 32 * p] = s4h[ln + 32 * p];
        dl[ln + 32 * p] = s4l[ln + 32 * p];
    }
}

__global__ void convert_input_staged(const float* __restrict__ in) {
    __shared__ __nv_bfloat16 sh[8][1024];
    __shared__ __nv_bfloat16 sl[8][1024];
    const int sK = blockIdx.x;
    const int w = threadIdx.x >> 5, ln = threadIdx.x & 31;
    const int r0 = (blockIdx.y * 8 + w) * 32;
    const float sc = g_scales[0][sK * 32 + ln];
    const int u = ln >> 3, e = ln & 7;
#pragma unroll 4
    for (int j = 0; j < 32; ++j) {
        float x = in[(size_t)(r0 + j) * QD + sK * 32 + ln] * sc;
        __nv_bfloat16 h = __float2bfloat16(x);
        __nv_bfloat16 l = __float2bfloat16(x - __bfloat162float(h));
        int pos = j * 32 + ((u ^ ((j >> 1) & 3)) << 3) + e;
        sh[w][pos] = h;
        sl[w][pos] = l;
    }
    __syncwarp();
    size_t rowbase = (size_t)sK * BATCH + r0;
    uint4* dh = (uint4*)(g_Ast_hi[0] + rowbase * 32);
    uint4* dl = (uint4*)(g_Ast_lo[0] + rowbase * 32);
    const uint4* s4h = (const uint4*)sh[w];
    const uint4* s4l = (const uint4*)sl[w];
#pragma unroll
    for (int p = 0; p < 4; ++p) {
        dh[ln + 32 * p] = s4h[ln + 32 * p];
        dl[ln + 32 * p] = s4l[ln + 32 * p];
    }
}

// ---------------------------------------------------------------------------
// Persistent 17-layer chained GEMM. Grid (8,16) = 128 CTAs = one wave.
// CTA tile 256x256 for all layers. Per-chunk gmem flags pipeline the layer
// transition; producer polls them warp-cooperatively (32 flags / round trip).
// Warps 0-7: epilogue. Warp 8: bulk producer. Warp 9: MMA.
// ---------------------------------------------------------------------------
#define BM 256
#define BN 256
#define NSTAGE 3
#define TILE_B 16384
#define STAGE_B (4 * TILE_B)  // 64KB
#define K_ITERS KSTAGES       // 64
#define EPI_SMEM 32768        // 8 warps x 4KB staging
#define MMA_IDESC 0x8400490u  // F32 acc, BF16 a/b, M=128, N=256

__global__ __launch_bounds__(320, 1)
void qgemm_persistent(float* __restrict__ outF) {
#if HAS_TCGEN05
    extern __shared__ __align__(1024) char smem_dyn[];
    __shared__ __align__(8) unsigned long long s_bars[7];
    __shared__ uint32_t s_tmem;

    const int tid = threadIdx.x;
    const int wid = tid >> 5;
    const int lid = tid & 31;

    const uint32_t raw = smem_u32(smem_dyn);
    const uint32_t smem_base = (raw + 1023u) & ~1023u;
    char* smem_g = smem_dyn + (smem_base - raw);

    uint32_t bar_full[3], bar_empty[3], bar_done;
#pragma unroll
    for (int i = 0; i < 3; ++i) {
        bar_full[i]  = smem_u32(&s_bars[i]);
        bar_empty[i] = smem_u32(&s_bars[3 + i]);
    }
    bar_done = smem_u32(&s_bars[6]);

    if (tid == 0) {
#pragma unroll
        for (int i = 0; i < 3; ++i) {
            MBARRIER_INIT(bar_full[i], 1);
            MBARRIER_INIT(bar_empty[i], 1);
        }
        MBARRIER_INIT(bar_done, 1);
    }
    if (wid == 8) TCGEN05_ALLOC(smem_u32(&s_tmem), 512);
    __syncthreads();
    const uint32_t tmem_d = s_tmem;

    const int mi = blockIdx.y;
    const int ni = blockIdx.x;
    const int blockN = ni * BN;
    const int blockM = mi * BM;
    const size_t MATB = (size_t)KSTAGES * QD * 64;

    if (wid == 8) {
        // ---- producer warp (all lanes poll; one lane issues copies) -----
        int s = 0, w = 0;
        for (int l = 0; l < NMAT; ++l) {
            // ready bitmask over this layer's 64 stage-flags (layer l reads
            // A produced by layer l-1; layer 0 is ready by definition)
            unsigned long long ready = (l == 0) ? ~0ull : 0ull;
            for (int k = 0; k < K_ITERS; ++k) {
                if (l * K_ITERS + k >= NSTAGE)
                    MBARRIER_WAIT_PARITY(bar_empty[s], (w + 1) & 1);
                const uint32_t stage = smem_base + s * STAGE_B;
                const uint32_t ep = elect_one_pred();
                if (ep) MBARRIER_EXPECT_TX(bar_full[s], STAGE_B);
                // B (weights): no dependency, issue first
                const size_t boff = (size_t)l * MATB + ((size_t)k * QD + blockN) * 64;
                if (ep) {
                    bulk_cp(stage + 2 * TILE_B, (const char*)g_Wst_hi + boff, TILE_B, bar_full[s]);
                    bulk_cp(stage + 3 * TILE_B, (const char*)g_Wst_lo + boff, TILE_B, bar_full[s]);
                }
                // A: warp-cooperative poll of prev-layer chunk flags
                while (!((ready >> k) & 1)) {
                    int idx = k + lid;
                    int v = 0;
                    if (idx < K_ITERS) {
                        const int* f = &g_flags[l - 1][mi][idx >> 3][idx & 7];
                        asm volatile("ld.acquire.gpu.global.b32 %0, [%1];"
                                     : "=r"(v) : "l"(f) : "memory");
                    }
                    unsigned b = __ballot_sync(0xFFFFFFFFu, v >= 8);
                    ready |= ((unsigned long long)b) << k;
                }
                if (ep) {
                    asm volatile("fence.proxy.async;" ::: "memory");
                    const int pb = l & 1;
                    const size_t aoff = ((size_t)k * BATCH + blockM) * 64;
                    bulk_cp(stage,          (const char*)g_Ast_hi[pb] + aoff, TILE_B, bar_full[s]);
                    bulk_cp(stage + TILE_B, (const char*)g_Ast_lo[pb] + aoff, TILE_B, bar_full[s]);
                }
                if (++s == NSTAGE) { s = 0; ++w; }
            }
        }
    } else if (wid == 9) {
        // ---- MMA warp ---------------------------------------------------
        int s = 0, w = 0;
        for (int l = 0; l < NMAT; ++l) {
            asm volatile("bar.sync 1, 288;" ::: "memory");  // TMEM free handoff
            TCGEN05_FENCE_AFTER();
            for (int k = 0; k < K_ITERS; ++k) {
                MBARRIER_WAIT_PARITY(bar_full[s], w & 1);
                const uint32_t stage = smem_base + s * STAGE_B;
                if (elect_one_pred()) {
                    const uint64_t dBh = MAKE_DESC64(stage + 2 * TILE_B);
                    const uint64_t dBl = MAKE_DESC64(stage + 3 * TILE_B);
#pragma unroll
                    for (int h = 0; h < 2; ++h) {
                        const uint64_t dAh = MAKE_DESC64(stage + h * 8192);
                        const uint64_t dAl = MAKE_DESC64(stage + TILE_B + h * 8192);
                        const uint32_t d = tmem_d + h * 256;
#pragma unroll
                        for (int c = 0; c < 2; ++c) {
                            uint32_t en0 = (k == 0 && c == 0) ? 0u : 1u;
                            mma_f16_ss(d, dAh + 2 * c, dBh + 2 * c, MMA_IDESC, en0);
                            mma_f16_ss(d, dAh + 2 * c, dBl + 2 * c, MMA_IDESC, 1);
                            mma_f16_ss(d, dAl + 2 * c, dBh + 2 * c, MMA_IDESC, 1);
                        }
                    }
                    TCGEN05_COMMIT(bar_empty[s]);
                }
                if (++s == NSTAGE) { s = 0; ++w; }
            }
            if (elect_one_pred()) TCGEN05_COMMIT(bar_done);
        }
    } else {
        // ---- epilogue warps 0-7 ----------------------------------------
        const int half = wid >> 2;
        const int rbase = blockM + half * 128 + (wid & 3) * 32;
        const int row = rbase + lid;
        const int uperm = (lid >> 1) & 3;
        char* wsm = smem_g + NSTAGE * STAGE_B + wid * 4096;  // 2KB hi + 2KB lo
        for (int l = 0; l < NMAT; ++l) {
            asm volatile("bar.sync 1, 288;" ::: "memory");
            MBARRIER_WAIT_PARITY(bar_done, l & 1);
            TCGEN05_FENCE_AFTER();
            const float* scaleNext = (l < L_LAYERS - 1) ? g_scales[l + 1] : nullptr;
            const int fpout = (l == NMAT - 1);
            const int wb = (l + 1) & 1;
            __nv_bfloat16* outHi = g_Ast_hi[wb];
            __nv_bfloat16* outLo = g_Ast_lo[wb];
#pragma unroll 1
            for (int ch = 0; ch < 8; ++ch) {
                uint32_t regs[32];
                TCGEN05_LD_32X32B_X32(regs, tmem_d + half * 256 + ch * 32);
                TCGEN05_WAIT_LD();
                const int c0 = blockN + ch * 32;
                if (fpout) {
                    float* dst = outF + (size_t)row * QD + c0;
#pragma unroll
                    for (int g = 0; g < 8; ++g)
                        *(float4*)(dst + g * 4) = make_float4(
                            __uint_as_float(regs[g * 4 + 0]), __uint_as_float(regs[g * 4 + 1]),
                            __uint_as_float(regs[g * 4 + 2]), __uint_as_float(regs[g * 4 + 3]));
                } else {
                    uint32_t hp[16], lp[16];
#pragma unroll
                    for (int q = 0; q < 16; ++q) {
                        float v0 = __uint_as_float(regs[2 * q]);
                        float v1 = __uint_as_float(regs[2 * q + 1]);
                        if (scaleNext) {
                            const float2 s2 = *(const float2*)(scaleNext + c0 + 2 * q);
                            v0 *= s2.x;
                            v1 *= s2.y;
                        }
                        // truncation split: hi = top 16 bits, lo = v - hi
                        uint32_t b0 = __float_as_uint(v0), b1 = __float_as_uint(v1);
                        float lo0 = v0 - __uint_as_float(b0 & 0xFFFF0000u);
                        float lo1 = v1 - __uint_as_float(b1 & 0xFFFF0000u);
                        uint32_t h;
                        asm("prmt.b32 %0, %1, %2, 0x7632;" : "=r"(h) : "r"(b0), "r"(b1));
                        hp[q] = h;
                        uint32_t lpk;
                        asm("cvt.rn.bf16x2.f32 %0, %1, %2;" : "=r"(lpk) : "f"(lo1), "f"(lo0));
                        lp[q] = lpk;
                    }
                    // stage into smem (swizzled), then coalesced 2KB copy-out
#pragma unroll
                    for (int u = 0; u < 4; ++u) {
                        int up = (u ^ uperm) << 4;
                        *(uint4*)(wsm + lid * 64 + up) =
                            make_uint4(hp[4 * u], hp[4 * u + 1], hp[4 * u + 2], hp[4 * u + 3]);
                        *(uint4*)(wsm + 2048 + lid * 64 + up) =
                            make_uint4(lp[4 * u], lp[4 * u + 1], lp[4 * u + 2], lp[4 * u + 3]);
                    }
                    __syncwarp();
                    const int sK = c0 >> 5;
                    size_t rowbase = (size_t)sK * BATCH + rbase;
                    uint4* dh = (uint4*)(outHi + rowbase * 32);
                    uint4* dl = (uint4*)(outLo + rowbase * 32);
                    const uint4* s4h = (const uint4*)wsm;
                    const uint4* s4l = (const uint4*)(wsm + 2048);
#pragma unroll
                    for (int p = 0; p < 4; ++p) {
                        dh[lid + 32 * p] = s4h[lid + 32 * p];
                        dl[lid + 32 * p] = s4l[lid + 32 * p];
                    }
                    __syncwarp();
                    if (lid == 0) {
                        asm volatile("red.release.gpu.global.add.s32 [%0], 1;"
                                     :: "l"(&g_flags[l][mi][ni][ch]) : "memory");
                    }
                }
            }
            TCGEN05_FENCE_BEFORE();
        }
    }

    __syncthreads();
    if (wid == 8) {
        TCGEN05_RELINQUISH();
        TCGEN05_DEALLOC(tmem_d, 512);
    }
#endif  // HAS_TCGEN05
}

// ---------------------------------------------------------------------------
// Launch
// ---------------------------------------------------------------------------
extern "C" void kernel_launch(void* const* d_in, const int* in_sizes, int n_in,
                              void* d_out, int out_size) {
    const float* input_state = (const float*)d_in[0];
    const float* angles      = (const float*)d_in[1];
    const float* weights     = (const float*)d_in[2];
    const float* meas_basis  = (const float*)d_in[3];
    float* out = (float*)d_out;
    (void)in_sizes; (void)n_in; (void)out_size;

    const size_t dyn = NSTAGE * STAGE_B + EPI_SMEM + 1024;  // 225 KB
    cudaFuncSetAttribute(qgemm_persistent, cudaFuncAttributeMaxDynamicSharedMemorySize, dyn);

    prep_small_kernel<<<128, 256>>>(angles);
    convert_weights_staged<<<dim3(KSTAGES, QD / 256, NMAT), 256>>>(weights, meas_basis);
    convert_input_staged<<<dim3(KSTAGES, BATCH / 256), 256>>>(input_state);

    dim3 grid(QD / BN, BATCH / BM);  // (8, 16) = 128 CTAs, one wave
    qgemm_persistent<<<grid, 320, dyn>>>(out);
}